// round 3
// baseline (speedup 1.0000x reference)
#include <cuda_runtime.h>
#include <math.h>

#define N_ATOMS 1500
#define NODE_DIM 128
#define HIDDEN 64
#define SPH_DIM 480
#define OFF0 128
#define MUL1E 64
#define HID1E 32
#define NUM_BASIS 20
#define CUTOFF 5.0f

#define TB 512
#define TA 4

#define NPB 5
#define NB_NODE 300      /* 300*5 = 1500 exactly */
#define NB_TAB 4
#define TAB_N 4096
#define TAB_RANGE 10.0f

// node n: [coord.xyz, ni.xyz, nj.xyz] as 3x float4
__device__ float4 g_node[N_ATOMS * 3];
// 0.5*fc(d) sampled at i*TAB_RANGE/TAB_N, i = 0..TAB_N (+1 guard)
__device__ float g_fc[TAB_N + 2];

__device__ __forceinline__ float sigmoidf_(float x) {
    return 1.0f / (1.0f + __expf(-x));
}

// ---------------------------------------------------------------------------
// Stage 1: per-node MLPs, 5 nodes per block. Extra blocks build the fc table.
// Thread roles (384 threads):
//   [0,128)   scalar MLPs (2 sets x 64 hidden cols)
//   [128,320) spherical MLPs (2 sets x 32 hidden x 3 dims)
//   rest      help with loads
// ---------------------------------------------------------------------------
__global__ __launch_bounds__(384, 4) void node_kernel(
    const float* __restrict__ xs_g, const float* __restrict__ xsph,
    const float* __restrict__ coord,
    const float* __restrict__ Wsi1, const float* __restrict__ Wsi2,
    const float* __restrict__ Wsj1, const float* __restrict__ Wsj2,
    const float* __restrict__ Wpi1, const float* __restrict__ Wpi2,
    const float* __restrict__ Wpj1, const float* __restrict__ Wpj2,
    const float* __restrict__ Wrbf)
{
    int tid = threadIdx.x;

    if (blockIdx.x >= NB_NODE) {
        // ---- fc table build ----
        const float dO = CUTOFF / (float)(NUM_BASIS - 1);
        const float c2e = (-0.5f / (dO * dO)) * 1.4426950408889634f;
        float w[NUM_BASIS];
        #pragma unroll
        for (int k = 0; k < NUM_BASIS; k++) w[k] = __ldg(&Wrbf[k]);
        for (int i = (blockIdx.x - NB_NODE) * 384 + tid; i <= TAB_N + 1; i += NB_TAB * 384) {
            float x = (float)i * (TAB_RANGE / (float)TAB_N);
            float fc = 0.f;
            #pragma unroll
            for (int k = 0; k < NUM_BASIS; k++) {
                float t = x - (float)k * dO;
                fc = fmaf(w[k], exp2f((c2e * t) * t), fc);
            }
            g_fc[i] = 0.5f * fc;
        }
        return;
    }

    __shared__ __align__(16) float xs[NPB * NODE_DIM];   // 2.5 KB
    __shared__ float vv[NPB * 192];                      // 1e block per node
    __shared__ float hh[NPB * 192];                      // [n][set][hc][dd]
    __shared__ float hg[NPB * 192];
    __shared__ float sp[NPB * 128];                      // [n][set][col]
    __shared__ float outp[NPB][2][3];
    __shared__ float sred[NPB][2];

    int n0 = blockIdx.x * NPB;

    for (int i = tid; i < NPB * NODE_DIM; i += 384) xs[i] = xs_g[n0 * NODE_DIM + i];
    for (int i = tid; i < NPB * 192; i += 384) {
        int n = i / 192, k = i - n * 192;
        vv[i] = xsph[(size_t)(n0 + n) * SPH_DIM + OFF0 + k];
    }
    __syncthreads();

    if (tid < 128) {
        int set = tid >> 6, col = tid & 63;
        const float* W1 = set ? Wsj1 : Wsi1;
        const float* W2 = set ? Wsj2 : Wsi2;
        float acc[NPB];
        #pragma unroll
        for (int n = 0; n < NPB; n++) acc[n] = 0.f;
        const float4* xs4 = (const float4*)xs;
        #pragma unroll 4
        for (int k = 0; k < NODE_DIM; k += 4) {
            float w0 = __ldg(&W1[(k + 0) * HIDDEN + col]);
            float w1 = __ldg(&W1[(k + 1) * HIDDEN + col]);
            float w2 = __ldg(&W1[(k + 2) * HIDDEN + col]);
            float w3 = __ldg(&W1[(k + 3) * HIDDEN + col]);
            #pragma unroll
            for (int n = 0; n < NPB; n++) {
                float4 x = xs4[n * (NODE_DIM / 4) + (k >> 2)];
                acc[n] = fmaf(x.x, w0, acc[n]);
                acc[n] = fmaf(x.y, w1, acc[n]);
                acc[n] = fmaf(x.z, w2, acc[n]);
                acc[n] = fmaf(x.w, w3, acc[n]);
            }
        }
        float w2c = __ldg(&W2[col]);
        #pragma unroll
        for (int n = 0; n < NPB; n++) {
            float a = acc[n];
            float s = a * sigmoidf_(a);          // silu
            sp[n * 128 + set * 64 + col] = s * w2c;
        }
    } else if (tid < 320) {
        int t = tid - 128;
        int set = t / 96;
        int r = t - set * 96;
        int hc = r / 3, dd = r - hc * 3;
        const float* W1 = set ? Wpj1 : Wpi1;
        float acc[NPB];
        #pragma unroll
        for (int n = 0; n < NPB; n++) acc[n] = 0.f;
        #pragma unroll 4
        for (int m = 0; m < MUL1E; m++) {
            float w = __ldg(&W1[m * HID1E + hc]);
            #pragma unroll
            for (int n = 0; n < NPB; n++)
                acc[n] = fmaf(vv[n * 192 + m * 3 + dd], w, acc[n]);
        }
        #pragma unroll
        for (int n = 0; n < NPB; n++)
            hh[n * 192 + set * 96 + hc * 3 + dd] = acc[n] * 0.125f;   // 1/sqrt(64)
    }
    __syncthreads();

    if (tid >= 128 && tid < 320) {
        int t = tid - 128;
        int set = t / 96;
        int r = t - set * 96;
        int hc = r / 3, dd = r - hc * 3;
        const float* W2 = set ? Wpj2 : Wpi2;
        float w2c = __ldg(&W2[hc]);
        #pragma unroll
        for (int n = 0; n < NPB; n++) {
            int base = n * 192 + set * 96 + hc * 3;
            float h0 = hh[base + 0], h1 = hh[base + 1], h2 = hh[base + 2];
            float nrm = sqrtf(h0 * h0 + h1 * h1 + h2 * h2);
            float gate = sigmoidf_(nrm);
            hg[base + dd] = hh[base + dd] * gate * w2c;
        }
    }
    __syncthreads();

    if (tid < NPB * 6) {                       // (n, set, dd) spherical reduce
        int n = tid / 6;
        int r = tid - n * 6;
        int set = r / 3, dd = r - set * 3;
        float s = 0.f;
        for (int hc = 0; hc < HID1E; hc++) s += hg[n * 192 + set * 96 + hc * 3 + dd];
        outp[n][set][dd] = s * 0.17677669529663687f;   // 1/sqrt(32)
    } else if (tid >= 64 && tid < 64 + NPB * 2) {      // (n, set) scalar reduce
        int t = tid - 64;
        int n = t >> 1, set = t & 1;
        float s = 0.f;
        for (int col = 0; col < HIDDEN; col++) s += sp[n * 128 + set * 64 + col];
        sred[n][set] = s;
    }
    __syncthreads();

    if (tid < NPB) {
        int n = n0 + tid;
        float fi = 1.f + sred[tid][0];
        float fj = 1.f + sred[tid][1];
        // e3nn 1e (y,z,x) -> (x,y,z): out[:, [2,0,1]]
        g_node[n * 3 + 0] = make_float4(coord[n * 3 + 0], coord[n * 3 + 1], coord[n * 3 + 2], 0.f);
        g_node[n * 3 + 1] = make_float4(outp[tid][0][2] * fi, outp[tid][0][0] * fi, outp[tid][0][1] * fi, 0.f);
        g_node[n * 3 + 2] = make_float4(outp[tid][1][2] * fj, outp[tid][1][0] * fj, outp[tid][1][1] * fj, 0.f);
    }
}

// ---------------------------------------------------------------------------
// Stage 2: edges. Block = 512 b-values x TA=4 a-values.
// out[a*N+b][r][c] = 0.5 * fc(d_ab) * (ni_a[r]*nj_b[c] + nj_a[r]*ni_b[c])
// fc via smem lookup table + lerp; staged through smem for coalesced stores.
// ---------------------------------------------------------------------------
__global__ __launch_bounds__(TB, 3) void edge_kernel(float* __restrict__ out)
{
    __shared__ __align__(16) float stage[TB * 9];   // 18 KB
    __shared__ float tab[TAB_N + 2];                // 16 KB

    int tid = threadIdx.x;
    for (int i = tid; i <= TAB_N + 1; i += TB) tab[i] = g_fc[i];

    int b0 = blockIdx.x * TB;
    int b = b0 + tid;
    bool valid = b < N_ATOMS;

    float4 cb = {}, nib = {}, njb = {};
    if (valid) {
        cb  = g_node[b * 3 + 0];
        nib = g_node[b * 3 + 1];
        njb = g_node[b * 3 + 2];
    }
    const int nb = min(TB, N_ATOMS - b0);
    const float scale = (float)TAB_N / TAB_RANGE;   // 409.6
    __syncthreads();

    #pragma unroll
    for (int ai = 0; ai < TA; ai++) {
        int a = blockIdx.y * TA + ai;
        float4 ca  = g_node[a * 3 + 0];
        float4 nia = g_node[a * 3 + 1];
        float4 nja = g_node[a * 3 + 2];

        if (valid) {
            float dx = ca.x - cb.x, dy = ca.y - cb.y, dz = ca.z - cb.z;
            float d2 = fmaf(dx, dx, fmaf(dy, dy, dz * dz));
            float d;
            asm("sqrt.approx.f32 %0, %1;" : "=f"(d) : "f"(d2));  // sqrt(0)=0 ok

            float u = d * scale;
            int i = __float2int_rd(u);
            i = min(i, TAB_N - 1);
            float frac = u - (float)i;
            float t0 = tab[i], t1 = tab[i + 1];
            float f = fmaf(frac, t1 - t0, t0);      // 0.5*fc(d)

            float fjx = f * njb.x, fjy = f * njb.y, fjz = f * njb.z;
            float fax = f * nja.x, fay = f * nja.y, faz = f * nja.z;

            float* st = &stage[tid * 9];
            st[0] = fmaf(nia.x, fjx, fax * nib.x);
            st[1] = fmaf(nia.x, fjy, fax * nib.y);
            st[2] = fmaf(nia.x, fjz, fax * nib.z);
            st[3] = fmaf(nia.y, fjx, fay * nib.x);
            st[4] = fmaf(nia.y, fjy, fay * nib.y);
            st[5] = fmaf(nia.y, fjz, fay * nib.z);
            st[6] = fmaf(nia.z, fjx, faz * nib.x);
            st[7] = fmaf(nia.z, fjy, faz * nib.y);
            st[8] = fmaf(nia.z, fjz, faz * nib.z);
        }
        __syncthreads();

        // coalesced float4 copy: nb*9 is divisible by 4 for nb in {512, 476}
        const float4* s4 = (const float4*)stage;
        float4* d4 = (float4*)(out + ((size_t)a * N_ATOMS + b0) * 9);
        int tot4 = (nb * 9) >> 2;
        for (int idx = tid; idx < tot4; idx += TB) d4[idx] = s4[idx];
        __syncthreads();
    }
}

extern "C" void kernel_launch(void* const* d_in, const int* in_sizes, int n_in,
                              void* d_out, int out_size)
{
    const float* xs    = (const float*)d_in[0];
    const float* xsph  = (const float*)d_in[1];
    const float* coord = (const float*)d_in[2];
    // d_in[3] = fc_edge_index (full graph, i-major; structure known, unused)
    const float* Wsi1 = (const float*)d_in[4];
    const float* Wsi2 = (const float*)d_in[5];
    const float* Wsj1 = (const float*)d_in[6];
    const float* Wsj2 = (const float*)d_in[7];
    const float* Wpi1 = (const float*)d_in[8];
    const float* Wpi2 = (const float*)d_in[9];
    const float* Wpj1 = (const float*)d_in[10];
    const float* Wpj2 = (const float*)d_in[11];
    const float* Wrbf = (const float*)d_in[12];

    node_kernel<<<NB_NODE + NB_TAB, 384>>>(xs, xsph, coord,
                                           Wsi1, Wsi2, Wsj1, Wsj2,
                                           Wpi1, Wpi2, Wpj1, Wpj2, Wrbf);

    dim3 grid((N_ATOMS + TB - 1) / TB, N_ATOMS / TA);
    edge_kernel<<<grid, TB>>>((float*)d_out);
}

// round 4
// speedup vs baseline: 1.1572x; 1.1572x over previous
#include <cuda_runtime.h>
#include <math.h>

#define N_ATOMS 1500
#define NODE_DIM 128
#define HIDDEN 64
#define SPH_DIM 480
#define OFF0 128
#define MUL1E 64
#define HID1E 32
#define NUM_BASIS 20
#define CUTOFF 5.0f

#define TB 256
#define TE 4                 /* edges per thread */
#define BTILE (TB * TE)      /* 1024 b's per block; 1500 = 1024 + 476, 476 = 4*119 */
#define TA 4

#define NPB 10
#define NB_NODE 150          /* 150*10 = 1500 exactly */
#define NB_TAB 4
#define TAB_N 1024
#define TAB_RANGE 8.0f       /* fc underflows to 0 beyond d ~ 8 */

// node n: [coord.xyz, ni.xyz, nj.xyz] as 3x float4
__device__ float4 g_node[N_ATOMS * 3];
// 0.5*fc(d) sampled at i*TAB_RANGE/TAB_N, i = 0..TAB_N (+1 guard)
__device__ float g_fc[TAB_N + 2];

__device__ __forceinline__ float sigmoidf_(float x) {
    return 1.0f / (1.0f + __expf(-x));
}

__device__ __forceinline__ unsigned smem_u32(const void* p) {
    unsigned a;
    asm("{ .reg .u64 t; cvta.to.shared.u64 t, %1; cvt.u32.u64 %0, t; }"
        : "=r"(a) : "l"(p));
    return a;
}

// ---------------------------------------------------------------------------
// Stage 1: per-node MLPs, 10 nodes per block. Extra blocks build the fc table.
// Thread roles (384 threads):
//   [0,128)   scalar MLPs (2 sets x 64 hidden cols)
//   [128,320) spherical MLPs (2 sets x 32 hidden x 3 dims)
// ---------------------------------------------------------------------------
__global__ __launch_bounds__(384) void node_kernel(
    const float* __restrict__ xs_g, const float* __restrict__ xsph,
    const float* __restrict__ coord,
    const float* __restrict__ Wsi1, const float* __restrict__ Wsi2,
    const float* __restrict__ Wsj1, const float* __restrict__ Wsj2,
    const float* __restrict__ Wpi1, const float* __restrict__ Wpi2,
    const float* __restrict__ Wpj1, const float* __restrict__ Wpj2,
    const float* __restrict__ Wrbf)
{
    int tid = threadIdx.x;

    if (blockIdx.x >= NB_NODE) {
        // ---- fc table build ----
        const float dO = CUTOFF / (float)(NUM_BASIS - 1);
        const float c2e = (-0.5f / (dO * dO)) * 1.4426950408889634f;
        float w[NUM_BASIS];
        #pragma unroll
        for (int k = 0; k < NUM_BASIS; k++) w[k] = __ldg(&Wrbf[k]);
        for (int i = (blockIdx.x - NB_NODE) * 384 + tid; i <= TAB_N + 1; i += NB_TAB * 384) {
            float x = (float)i * (TAB_RANGE / (float)TAB_N);
            float fc = 0.f;
            #pragma unroll
            for (int k = 0; k < NUM_BASIS; k++) {
                float t = x - (float)k * dO;
                fc = fmaf(w[k], exp2f((c2e * t) * t), fc);
            }
            g_fc[i] = 0.5f * fc;
        }
        return;
    }

    __shared__ __align__(16) float xs[NPB * NODE_DIM];   // 5 KB
    __shared__ float vv[NPB * 192];                      // 7.5 KB
    __shared__ float hh[NPB * 192];
    __shared__ float hg[NPB * 192];
    __shared__ float sp[NPB * 128];
    __shared__ float outp[NPB][2][3];
    __shared__ float sred[NPB][2];

    int n0 = blockIdx.x * NPB;

    for (int i = tid; i < NPB * NODE_DIM; i += 384) xs[i] = xs_g[n0 * NODE_DIM + i];
    for (int i = tid; i < NPB * 192; i += 384) {
        int n = i / 192, k = i - n * 192;
        vv[i] = xsph[(size_t)(n0 + n) * SPH_DIM + OFF0 + k];
    }
    __syncthreads();

    if (tid < 128) {
        int set = tid >> 6, col = tid & 63;
        const float* W1 = set ? Wsj1 : Wsi1;
        const float* W2 = set ? Wsj2 : Wsi2;
        float acc[NPB];
        #pragma unroll
        for (int n = 0; n < NPB; n++) acc[n] = 0.f;
        const float4* xs4 = (const float4*)xs;
        #pragma unroll 2
        for (int k = 0; k < NODE_DIM; k += 4) {
            float w0 = __ldg(&W1[(k + 0) * HIDDEN + col]);
            float w1 = __ldg(&W1[(k + 1) * HIDDEN + col]);
            float w2 = __ldg(&W1[(k + 2) * HIDDEN + col]);
            float w3 = __ldg(&W1[(k + 3) * HIDDEN + col]);
            #pragma unroll
            for (int n = 0; n < NPB; n++) {
                float4 x = xs4[n * (NODE_DIM / 4) + (k >> 2)];
                acc[n] = fmaf(x.x, w0, acc[n]);
                acc[n] = fmaf(x.y, w1, acc[n]);
                acc[n] = fmaf(x.z, w2, acc[n]);
                acc[n] = fmaf(x.w, w3, acc[n]);
            }
        }
        float w2c = __ldg(&W2[col]);
        #pragma unroll
        for (int n = 0; n < NPB; n++) {
            float a = acc[n];
            float s = a * sigmoidf_(a);          // silu
            sp[n * 128 + set * 64 + col] = s * w2c;
        }
    } else if (tid < 320) {
        int t = tid - 128;
        int set = t / 96;
        int r = t - set * 96;
        int hc = r / 3, dd = r - hc * 3;
        const float* W1 = set ? Wpj1 : Wpi1;
        float acc[NPB];
        #pragma unroll
        for (int n = 0; n < NPB; n++) acc[n] = 0.f;
        #pragma unroll 4
        for (int m = 0; m < MUL1E; m++) {
            float w = __ldg(&W1[m * HID1E + hc]);
            #pragma unroll
            for (int n = 0; n < NPB; n++)
                acc[n] = fmaf(vv[n * 192 + m * 3 + dd], w, acc[n]);
        }
        #pragma unroll
        for (int n = 0; n < NPB; n++)
            hh[n * 192 + set * 96 + hc * 3 + dd] = acc[n] * 0.125f;   // 1/sqrt(64)
    }
    __syncthreads();

    if (tid >= 128 && tid < 320) {
        int t = tid - 128;
        int set = t / 96;
        int r = t - set * 96;
        int hc = r / 3, dd = r - hc * 3;
        const float* W2 = set ? Wpj2 : Wpi2;
        float w2c = __ldg(&W2[hc]);
        #pragma unroll
        for (int n = 0; n < NPB; n++) {
            int base = n * 192 + set * 96 + hc * 3;
            float h0 = hh[base + 0], h1 = hh[base + 1], h2 = hh[base + 2];
            float nrm = sqrtf(h0 * h0 + h1 * h1 + h2 * h2);
            float gate = sigmoidf_(nrm);
            hg[base + dd] = hh[base + dd] * gate * w2c;
        }
    }
    __syncthreads();

    if (tid < NPB * 6) {                       // (n, set, dd) spherical reduce
        int n = tid / 6;
        int r = tid - n * 6;
        int set = r / 3, dd = r - set * 3;
        float s = 0.f;
        for (int hc = 0; hc < HID1E; hc++) s += hg[n * 192 + set * 96 + hc * 3 + dd];
        outp[n][set][dd] = s * 0.17677669529663687f;   // 1/sqrt(32)
    } else if (tid >= 64 && tid < 64 + NPB * 2) {      // (n, set) scalar reduce
        int t = tid - 64;
        int n = t >> 1, set = t & 1;
        float s = 0.f;
        for (int col = 0; col < HIDDEN; col++) s += sp[n * 128 + set * 64 + col];
        sred[n][set] = s;
    }
    __syncthreads();

    if (tid < NPB) {
        int n = n0 + tid;
        float fi = 1.f + sred[tid][0];
        float fj = 1.f + sred[tid][1];
        // e3nn 1e (y,z,x) -> (x,y,z): out[:, [2,0,1]]
        g_node[n * 3 + 0] = make_float4(coord[n * 3 + 0], coord[n * 3 + 1], coord[n * 3 + 2], 0.f);
        g_node[n * 3 + 1] = make_float4(outp[tid][0][2] * fi, outp[tid][0][0] * fi, outp[tid][0][1] * fi, 0.f);
        g_node[n * 3 + 2] = make_float4(outp[tid][1][2] * fj, outp[tid][1][0] * fj, outp[tid][1][1] * fj, 0.f);
    }
}

// ---------------------------------------------------------------------------
// Stage 2: edges. 256 threads x 4 edges each = 1024-b tile, x TA=4 a-values.
// out[a*N+b][r][c] = 0.5 * fc(d_ab) * (ni_a[r]*nj_b[c] + nj_a[r]*ni_b[c])
// Each thread stages its 36 floats as 9 aligned float4s; the stage->global
// copy is done by the TMA bulk engine (cp.async.bulk S2G), freeing SM pipes.
// ---------------------------------------------------------------------------
__global__ __launch_bounds__(TB, 2) void edge_kernel(float* __restrict__ out)
{
    __shared__ __align__(16) float4 stage[BTILE * 9 / 4];   // 36 KB
    __shared__ float2 tab2[TAB_N + 1];                      // 8 KB

    int tid = threadIdx.x;
    for (int i = tid; i <= TAB_N; i += TB)
        tab2[i] = make_float2(g_fc[i], g_fc[i + 1]);

    int b0 = blockIdx.x * BTILE;
    int nb = min(BTILE, N_ATOMS - b0);       // 1024 or 476 (both /4)
    bool valid = (tid * TE) < nb;

    float4 cb[TE], nib[TE], njb[TE];
    if (valid) {
        #pragma unroll
        for (int e = 0; e < TE; e++) {
            int b = b0 + tid * TE + e;
            cb[e]  = g_node[b * 3 + 0];
            nib[e] = g_node[b * 3 + 1];
            njb[e] = g_node[b * 3 + 2];
        }
    }
    const float scale = (float)TAB_N / TAB_RANGE;
    const unsigned stage_sa = smem_u32(stage);
    __syncthreads();

    #pragma unroll
    for (int ai = 0; ai < TA; ai++) {
        int a = blockIdx.y * TA + ai;
        float4 ca  = __ldg(&((const float4*)g_node)[a * 3 + 0]);
        float4 nia = __ldg(&((const float4*)g_node)[a * 3 + 1]);
        float4 nja = __ldg(&((const float4*)g_node)[a * 3 + 2]);

        float o[36];
        if (valid) {
            #pragma unroll
            for (int e = 0; e < TE; e++) {
                float dx = ca.x - cb[e].x, dy = ca.y - cb[e].y, dz = ca.z - cb[e].z;
                float d2 = fmaf(dx, dx, fmaf(dy, dy, dz * dz));
                float d;
                asm("sqrt.approx.f32 %0, %1;" : "=f"(d) : "f"(d2));  // sqrt(0)=0 ok

                float u = fminf(d * scale, (float)TAB_N - 1.0f);
                int i = __float2int_rd(u);
                float frac = u - (float)i;
                float2 t = tab2[i];
                float f = fmaf(frac, t.y - t.x, t.x);      // 0.5*fc(d)

                float fjx = f * njb[e].x, fjy = f * njb[e].y, fjz = f * njb[e].z;
                float fax = f * nja.x,   fay = f * nja.y,   faz = f * nja.z;

                o[e * 9 + 0] = fmaf(nia.x, fjx, fax * nib[e].x);
                o[e * 9 + 1] = fmaf(nia.x, fjy, fax * nib[e].y);
                o[e * 9 + 2] = fmaf(nia.x, fjz, fax * nib[e].z);
                o[e * 9 + 3] = fmaf(nia.y, fjx, fay * nib[e].x);
                o[e * 9 + 4] = fmaf(nia.y, fjy, fay * nib[e].y);
                o[e * 9 + 5] = fmaf(nia.y, fjz, fay * nib[e].z);
                o[e * 9 + 6] = fmaf(nia.z, fjx, faz * nib[e].x);
                o[e * 9 + 7] = fmaf(nia.z, fjy, faz * nib[e].y);
                o[e * 9 + 8] = fmaf(nia.z, fjz, faz * nib[e].z);
            }
        }

        // wait for the previous TMA copy to finish before overwriting stage
        if (ai > 0) {
            if (tid == 0)
                asm volatile("cp.async.bulk.wait_group 0;" ::: "memory");
        }
        __syncthreads();

        if (valid) {
            float4* sp4 = &stage[tid * 9];
            #pragma unroll
            for (int q = 0; q < 9; q++)
                sp4[q] = make_float4(o[q * 4 + 0], o[q * 4 + 1], o[q * 4 + 2], o[q * 4 + 3]);
        }
        __syncthreads();

        if (tid == 0) {
            asm volatile("fence.proxy.async.shared::cta;" ::: "memory");
            float* gdst = out + ((size_t)a * N_ATOMS + b0) * 9;   // 16B aligned
            unsigned bytes = (unsigned)(nb * 9 * 4);              // 16B multiple
            asm volatile("cp.async.bulk.global.shared::cta.bulk_group [%0], [%1], %2;"
                         :: "l"(gdst), "r"(stage_sa), "r"(bytes) : "memory");
            asm volatile("cp.async.bulk.commit_group;" ::: "memory");
        }
    }

    if (tid == 0)
        asm volatile("cp.async.bulk.wait_group 0;" ::: "memory");
}

extern "C" void kernel_launch(void* const* d_in, const int* in_sizes, int n_in,
                              void* d_out, int out_size)
{
    const float* xs    = (const float*)d_in[0];
    const float* xsph  = (const float*)d_in[1];
    const float* coord = (const float*)d_in[2];
    // d_in[3] = fc_edge_index (full graph, i-major; structure known, unused)
    const float* Wsi1 = (const float*)d_in[4];
    const float* Wsi2 = (const float*)d_in[5];
    const float* Wsj1 = (const float*)d_in[6];
    const float* Wsj2 = (const float*)d_in[7];
    const float* Wpi1 = (const float*)d_in[8];
    const float* Wpi2 = (const float*)d_in[9];
    const float* Wpj1 = (const float*)d_in[10];
    const float* Wpj2 = (const float*)d_in[11];
    const float* Wrbf = (const float*)d_in[12];

    node_kernel<<<NB_NODE + NB_TAB, 384>>>(xs, xsph, coord,
                                           Wsi1, Wsi2, Wsj1, Wsj2,
                                           Wpi1, Wpi2, Wpj1, Wpj2, Wrbf);

    dim3 grid((N_ATOMS + BTILE - 1) / BTILE, N_ATOMS / TA);
    edge_kernel<<<grid, TB>>>((float*)d_out);
}

// round 9
// speedup vs baseline: 1.7404x; 1.5040x over previous
#include <cuda_runtime.h>
#include <math.h>

#define N_ATOMS 1500
#define NODE_DIM 128
#define HIDDEN 64
#define SPH_DIM 480
#define OFF0 128
#define MUL1E 64
#define HID1E 32
#define NUM_BASIS 20
#define CUTOFF 5.0f

#define TB 256
#define TE 2                 /* edges per thread */
#define BTILE (TB * TE)      /* 512 b's per block: 1500 = 512+512+476 */
#define TA 4

#define NPB 5
#define NB_NODE 300          /* 300*5 = 1500 exactly */
#define NB_TAB 4
#define TAB_N 1024
#define TAB_RANGE 8.0f       /* fc underflows to 0 beyond d ~ 8 */

// node n: [coord.xyz, ni.xyz, nj.xyz] as 3x float4
__device__ float4 g_node[N_ATOMS * 3];
// 0.5*fc(d) sampled at i*TAB_RANGE/TAB_N, i = 0..TAB_N (+1 guard)
__device__ float g_fc[TAB_N + 2];

__device__ __forceinline__ float sigmoidf_(float x) {
    return 1.0f / (1.0f + __expf(-x));
}

__device__ __forceinline__ unsigned smem_u32(const void* p) {
    unsigned a;
    asm("{ .reg .u64 t; cvta.to.shared.u64 t, %1; cvt.u32.u64 %0, t; }"
        : "=r"(a) : "l"(p));
    return a;
}

// ---------------------------------------------------------------------------
// Stage 1: per-node MLPs, 5 nodes per block. Extra blocks build the fc table.
// Thread roles (384 threads):
//   [0,128)   scalar MLPs (2 sets x 64 hidden cols)
//   [128,320) spherical MLPs (2 sets x 32 hidden x 3 dims)
// ---------------------------------------------------------------------------
__global__ __launch_bounds__(384, 4) void node_kernel(
    const float* __restrict__ xs_g, const float* __restrict__ xsph,
    const float* __restrict__ coord,
    const float* __restrict__ Wsi1, const float* __restrict__ Wsi2,
    const float* __restrict__ Wsj1, const float* __restrict__ Wsj2,
    const float* __restrict__ Wpi1, const float* __restrict__ Wpi2,
    const float* __restrict__ Wpj1, const float* __restrict__ Wpj2,
    const float* __restrict__ Wrbf)
{
    int tid = threadIdx.x;

    if (blockIdx.x >= NB_NODE) {
        // ---- fc table build ----
        const float dO = CUTOFF / (float)(NUM_BASIS - 1);
        const float c2e = (-0.5f / (dO * dO)) * 1.4426950408889634f;
        float w[NUM_BASIS];
        #pragma unroll
        for (int k = 0; k < NUM_BASIS; k++) w[k] = __ldg(&Wrbf[k]);
        for (int i = (blockIdx.x - NB_NODE) * 384 + tid; i <= TAB_N + 1; i += NB_TAB * 384) {
            float x = (float)i * (TAB_RANGE / (float)TAB_N);
            float fc = 0.f;
            #pragma unroll
            for (int k = 0; k < NUM_BASIS; k++) {
                float t = x - (float)k * dO;
                fc = fmaf(w[k], exp2f((c2e * t) * t), fc);
            }
            g_fc[i] = 0.5f * fc;
        }
        return;
    }

    __shared__ __align__(16) float xs[NPB * NODE_DIM];   // 2.5 KB
    __shared__ float vv[NPB * 192];
    __shared__ float hh[NPB * 192];
    __shared__ float hg[NPB * 192];
    __shared__ float sp[NPB * 128];
    __shared__ float outp[NPB][2][3];
    __shared__ float sred[NPB][2];

    int n0 = blockIdx.x * NPB;

    for (int i = tid; i < NPB * NODE_DIM; i += 384) xs[i] = xs_g[n0 * NODE_DIM + i];
    for (int i = tid; i < NPB * 192; i += 384) {
        int n = i / 192, k = i - n * 192;
        vv[i] = xsph[(size_t)(n0 + n) * SPH_DIM + OFF0 + k];
    }
    __syncthreads();

    if (tid < 128) {
        int set = tid >> 6, col = tid & 63;
        const float* W1 = set ? Wsj1 : Wsi1;
        const float* W2 = set ? Wsj2 : Wsi2;
        float acc[NPB];
        #pragma unroll
        for (int n = 0; n < NPB; n++) acc[n] = 0.f;
        const float4* xs4 = (const float4*)xs;
        #pragma unroll 4
        for (int k = 0; k < NODE_DIM; k += 4) {
            float w0 = __ldg(&W1[(k + 0) * HIDDEN + col]);
            float w1 = __ldg(&W1[(k + 1) * HIDDEN + col]);
            float w2 = __ldg(&W1[(k + 2) * HIDDEN + col]);
            float w3 = __ldg(&W1[(k + 3) * HIDDEN + col]);
            #pragma unroll
            for (int n = 0; n < NPB; n++) {
                float4 x = xs4[n * (NODE_DIM / 4) + (k >> 2)];
                acc[n] = fmaf(x.x, w0, acc[n]);
                acc[n] = fmaf(x.y, w1, acc[n]);
                acc[n] = fmaf(x.z, w2, acc[n]);
                acc[n] = fmaf(x.w, w3, acc[n]);
            }
        }
        float w2c = __ldg(&W2[col]);
        #pragma unroll
        for (int n = 0; n < NPB; n++) {
            float a = acc[n];
            float s = a * sigmoidf_(a);          // silu
            sp[n * 128 + set * 64 + col] = s * w2c;
        }
    } else if (tid < 320) {
        int t = tid - 128;
        int set = t / 96;
        int r = t - set * 96;
        int hc = r / 3, dd = r - hc * 3;
        const float* W1 = set ? Wpj1 : Wpi1;
        float acc[NPB];
        #pragma unroll
        for (int n = 0; n < NPB; n++) acc[n] = 0.f;
        #pragma unroll 4
        for (int m = 0; m < MUL1E; m++) {
            float w = __ldg(&W1[m * HID1E + hc]);
            #pragma unroll
            for (int n = 0; n < NPB; n++)
                acc[n] = fmaf(vv[n * 192 + m * 3 + dd], w, acc[n]);
        }
        #pragma unroll
        for (int n = 0; n < NPB; n++)
            hh[n * 192 + set * 96 + hc * 3 + dd] = acc[n] * 0.125f;   // 1/sqrt(64)
    }
    __syncthreads();

    if (tid >= 128 && tid < 320) {
        int t = tid - 128;
        int set = t / 96;
        int r = t - set * 96;
        int hc = r / 3, dd = r - hc * 3;
        const float* W2 = set ? Wpj2 : Wpi2;
        float w2c = __ldg(&W2[hc]);
        #pragma unroll
        for (int n = 0; n < NPB; n++) {
            int base = n * 192 + set * 96 + hc * 3;
            float h0 = hh[base + 0], h1 = hh[base + 1], h2 = hh[base + 2];
            float nrm = sqrtf(h0 * h0 + h1 * h1 + h2 * h2);
            float gate = sigmoidf_(nrm);
            hg[base + dd] = hh[base + dd] * gate * w2c;
        }
    }
    __syncthreads();

    if (tid < NPB * 6) {                       // (n, set, dd) spherical reduce
        int n = tid / 6;
        int r = tid - n * 6;
        int set = r / 3, dd = r - set * 3;
        float s = 0.f;
        for (int hc = 0; hc < HID1E; hc++) s += hg[n * 192 + set * 96 + hc * 3 + dd];
        outp[n][set][dd] = s * 0.17677669529663687f;   // 1/sqrt(32)
    } else if (tid >= 64 && tid < 64 + NPB * 2) {      // (n, set) scalar reduce
        int t = tid - 64;
        int n = t >> 1, set = t & 1;
        float s = 0.f;
        for (int col = 0; col < HIDDEN; col++) s += sp[n * 128 + set * 64 + col];
        sred[n][set] = s;
    }
    __syncthreads();

    if (tid < NPB) {
        int n = n0 + tid;
        float fi = 1.f + sred[tid][0];
        float fj = 1.f + sred[tid][1];
        // e3nn 1e (y,z,x) -> (x,y,z): out[:, [2,0,1]]
        g_node[n * 3 + 0] = make_float4(coord[n * 3 + 0], coord[n * 3 + 1], coord[n * 3 + 2], 0.f);
        g_node[n * 3 + 1] = make_float4(outp[tid][0][2] * fi, outp[tid][0][0] * fi, outp[tid][0][1] * fi, 0.f);
        g_node[n * 3 + 2] = make_float4(outp[tid][1][2] * fj, outp[tid][1][0] * fj, outp[tid][1][1] * fj, 0.f);
    }
}

// ---------------------------------------------------------------------------
// Stage 2: edges. 256 threads x 2 edges each = 512-b tile, x TA=4 a-values.
// out[a*N+b][r][c] = 0.5 * fc(d_ab) * (ni_a[r]*nj_b[c] + nj_a[r]*ni_b[c])
// Double-buffered smem stage + TMA bulk S2G copies: iteration ai waits only
// for the copy issued at ai-2, so TMA(ai-1) overlaps compute(ai).
// ---------------------------------------------------------------------------
__global__ __launch_bounds__(TB, 4) void edge_kernel(float* __restrict__ out)
{
    __shared__ __align__(16) float stage[2][BTILE * 9];  // 36 KB
    __shared__ float2 tab2[TAB_N + 1];                   // 8.2 KB

    int tid = threadIdx.x;
    for (int i = tid; i <= TAB_N; i += TB)
        tab2[i] = make_float2(g_fc[i], g_fc[i + 1]);

    int b0 = blockIdx.x * BTILE;
    int nb = min(BTILE, N_ATOMS - b0);       // 512 or 476 (both even)
    bool valid = (tid * TE) < nb;

    const float4* gn = (const float4*)g_node;
    float4 cb0 = {}, nib0 = {}, njb0 = {}, cb1 = {}, nib1 = {}, njb1 = {};
    if (valid) {
        int b = b0 + tid * TE;
        cb0  = __ldg(&gn[(b + 0) * 3 + 0]);
        nib0 = __ldg(&gn[(b + 0) * 3 + 1]);
        njb0 = __ldg(&gn[(b + 0) * 3 + 2]);
        cb1  = __ldg(&gn[(b + 1) * 3 + 0]);
        nib1 = __ldg(&gn[(b + 1) * 3 + 1]);
        njb1 = __ldg(&gn[(b + 1) * 3 + 2]);
    }
    const float scale = (float)TAB_N / TAB_RANGE;
    __syncthreads();

    #pragma unroll
    for (int ai = 0; ai < TA; ai++) {
        int a = blockIdx.y * TA + ai;
        float4 ca  = __ldg(&gn[a * 3 + 0]);
        float4 nia = __ldg(&gn[a * 3 + 1]);
        float4 nja = __ldg(&gn[a * 3 + 2]);

        // the copy issued from this buffer two iterations ago must be done
        if (ai >= 2 && tid == 0)
            asm volatile("cp.async.bulk.wait_group %0;" :: "n"(1) : "memory");
        __syncthreads();

        float* st = &stage[ai & 1][tid * TE * 9];
        if (valid) {
            #pragma unroll
            for (int e = 0; e < TE; e++) {
                float4 cbe  = e ? cb1 : cb0;
                float4 nibe = e ? nib1 : nib0;
                float4 njbe = e ? njb1 : njb0;

                float dx = ca.x - cbe.x, dy = ca.y - cbe.y, dz = ca.z - cbe.z;
                float d2 = fmaf(dx, dx, fmaf(dy, dy, dz * dz));
                float d;
                asm("sqrt.approx.f32 %0, %1;" : "=f"(d) : "f"(d2));  // sqrt(0)=0 ok

                float u = fminf(d * scale, (float)TAB_N - 1.0f);
                int i = __float2int_rd(u);
                float frac = u - (float)i;
                float2 t = tab2[i];
                float f = fmaf(frac, t.y - t.x, t.x);      // 0.5*fc(d)

                float fjx = f * njbe.x, fjy = f * njbe.y, fjz = f * njbe.z;
                float fax = f * nja.x,  fay = f * nja.y,  faz = f * nja.z;

                st[e * 9 + 0] = fmaf(nia.x, fjx, fax * nibe.x);
                st[e * 9 + 1] = fmaf(nia.x, fjy, fax * nibe.y);
                st[e * 9 + 2] = fmaf(nia.x, fjz, fax * nibe.z);
                st[e * 9 + 3] = fmaf(nia.y, fjx, fay * nibe.x);
                st[e * 9 + 4] = fmaf(nia.y, fjy, fay * nibe.y);
                st[e * 9 + 5] = fmaf(nia.y, fjz, fay * nibe.z);
                st[e * 9 + 6] = fmaf(nia.z, fjx, faz * nibe.x);
                st[e * 9 + 7] = fmaf(nia.z, fjy, faz * nibe.y);
                st[e * 9 + 8] = fmaf(nia.z, fjz, faz * nibe.z);
            }
        }
        __syncthreads();

        if (tid == 0) {
            asm volatile("fence.proxy.async.shared::cta;" ::: "memory");
            float* gdst = out + ((size_t)a * N_ATOMS + b0) * 9;   // 16B aligned
            unsigned bytes = (unsigned)(nb * 9 * 4);              // 16B multiple
            unsigned sa = smem_u32(&stage[ai & 1][0]);
            asm volatile("cp.async.bulk.global.shared::cta.bulk_group [%0], [%1], %2;"
                         :: "l"(gdst), "r"(sa), "r"(bytes) : "memory");
            asm volatile("cp.async.bulk.commit_group;" ::: "memory");
        }
    }

    // keep CTA (and its smem) alive until all outstanding copies drain
    if (tid == 0)
        asm volatile("cp.async.bulk.wait_group %0;" :: "n"(0) : "memory");
}

extern "C" void kernel_launch(void* const* d_in, const int* in_sizes, int n_in,
                              void* d_out, int out_size)
{
    const float* xs    = (const float*)d_in[0];
    const float* xsph  = (const float*)d_in[1];
    const float* coord = (const float*)d_in[2];
    // d_in[3] = fc_edge_index (full graph, i-major; structure known, unused)
    const float* Wsi1 = (const float*)d_in[4];
    const float* Wsi2 = (const float*)d_in[5];
    const float* Wsj1 = (const float*)d_in[6];
    const float* Wsj2 = (const float*)d_in[7];
    const float* Wpi1 = (const float*)d_in[8];
    const float* Wpi2 = (const float*)d_in[9];
    const float* Wpj1 = (const float*)d_in[10];
    const float* Wpj2 = (const float*)d_in[11];
    const float* Wrbf = (const float*)d_in[12];

    node_kernel<<<NB_NODE + NB_TAB, 384>>>(xs, xsph, coord,
                                           Wsi1, Wsi2, Wsj1, Wsj2,
                                           Wpi1, Wpi2, Wpj1, Wpj2, Wrbf);

    dim3 grid((N_ATOMS + BTILE - 1) / BTILE, N_ATOMS / TA);
    edge_kernel<<<grid, TB>>>((float*)d_out);
}